// round 2
// baseline (speedup 1.0000x reference)
#include <cuda_runtime.h>
#include <math.h>

#define S_TOTAL 8192
#define DM      1024
#define NHEAD   16
#define HDIM    64
#define CHUNKL  2048
#define NCHUNK  4

// Scratch (allocation-free rule: __device__ globals)
__device__ float g_q[S_TOTAL * DM];
__device__ float g_k[S_TOTAL * DM];
__device__ float g_v[S_TOTAL * DM];
__device__ float g_attn[S_TOTAL * DM];

// ---------------------------------------------------------------------------
// NT GEMM: C[m,n] = sum_k A[m,k] * B[n,k]
// A: [M,K] row-major, B: [N,K] row-major (i.e. W stored [out,in] -> x @ W.T)
// 128x128 tile, BK=8, 256 threads, 8x8 per thread.
// ---------------------------------------------------------------------------
__global__ void __launch_bounds__(256) gemm_nt(const float* __restrict__ A,
                                               const float* __restrict__ B,
                                               float* __restrict__ C,
                                               int M, int N, int K) {
    __shared__ float As[8][132];
    __shared__ float Bs[8][132];

    const int tid = threadIdx.x;
    const int tx = tid & 15;       // 0..15 -> n
    const int ty = tid >> 4;       // 0..15 -> m
    const int bm = blockIdx.x;
    const int bn = blockIdx.y;

    const float* Ab = A + (size_t)bm * 128 * K;
    const float* Bb = B + (size_t)bn * 128 * K;

    float c[8][8];
#pragma unroll
    for (int i = 0; i < 8; i++)
#pragma unroll
        for (int j = 0; j < 8; j++) c[i][j] = 0.f;

    const int lm  = tid >> 1;        // 0..127
    const int lk4 = (tid & 1) * 4;   // 0 or 4

    for (int k0 = 0; k0 < K; k0 += 8) {
        float4 va = *(const float4*)(Ab + (size_t)lm * K + k0 + lk4);
        float4 vb = *(const float4*)(Bb + (size_t)lm * K + k0 + lk4);
        As[lk4 + 0][lm] = va.x; As[lk4 + 1][lm] = va.y;
        As[lk4 + 2][lm] = va.z; As[lk4 + 3][lm] = va.w;
        Bs[lk4 + 0][lm] = vb.x; Bs[lk4 + 1][lm] = vb.y;
        Bs[lk4 + 2][lm] = vb.z; Bs[lk4 + 3][lm] = vb.w;
        __syncthreads();

#pragma unroll
        for (int kk = 0; kk < 8; kk++) {
            float a[8], b[8];
#pragma unroll
            for (int i = 0; i < 8; i++) a[i] = As[kk][ty * 8 + i];
#pragma unroll
            for (int j = 0; j < 8; j++) b[j] = Bs[kk][tx + j * 16];
#pragma unroll
            for (int i = 0; i < 8; i++)
#pragma unroll
                for (int j = 0; j < 8; j++) c[i][j] += a[i] * b[j];
        }
        __syncthreads();
    }

#pragma unroll
    for (int i = 0; i < 8; i++) {
        const int row = bm * 128 + ty * 8 + i;
#pragma unroll
        for (int j = 0; j < 8; j++) {
            const int col = bn * 128 + tx + j * 16;
            C[(size_t)row * N + col] = c[i][j];
        }
    }
}

// ---------------------------------------------------------------------------
// Chunk-local causal attention, hd=64. One thread per query row; 64 queries
// per block. Two-pass online softmax per 64-key tile. K and V share one smem
// tile buffer (stay < 48KB static smem).
// grid: (32 qblocks, 16 heads, 4 chunks), block: 64 threads
// ---------------------------------------------------------------------------
__global__ void __launch_bounds__(64) attn_kernel(const float* __restrict__ q,
                                                  const float* __restrict__ k,
                                                  const float* __restrict__ v,
                                                  float* __restrict__ o) {
    __shared__ float KV[64][64];    // K tile, then reused as V tile
    __shared__ float Sc[64][65];    // scores, padded

    const int t  = threadIdx.x;          // query within block
    const int qb = blockIdx.x;
    const int h  = blockIdx.y;
    const int ch = blockIdx.z;

    const int    qi   = qb * 64 + t;
    const size_t qrow = (size_t)(ch * CHUNKL + qi) * DM + h * HDIM;

    float qreg[64];
#pragma unroll
    for (int d = 0; d < 64; d += 4) {
        float4 x = *(const float4*)(q + qrow + d);
        qreg[d] = x.x; qreg[d + 1] = x.y; qreg[d + 2] = x.z; qreg[d + 3] = x.w;
    }

    float m = -INFINITY, l = 0.f;
    float acc[64];
#pragma unroll
    for (int d = 0; d < 64; d++) acc[d] = 0.f;

    for (int kb = 0; kb <= qb; kb++) {
        const size_t tbase = (size_t)(ch * CHUNKL + kb * 64) * DM + h * HDIM;

        __syncthreads();   // prior tile fully consumed
        // --- load K tile (64 rows x 64 cols), float4, coalesced ---
#pragma unroll
        for (int i = 0; i < 16; i++) {
            int idx = t + i * 64;            // float4 index in 64x16 grid
            int j = idx >> 4, d4 = (idx & 15) << 2;
            *(float4*)&KV[j][d4] = *(const float4*)(k + tbase + (size_t)j * DM + d4);
        }
        __syncthreads();

        // --- pass 1: scores + tile max ---
        float mtile = -INFINITY;
#pragma unroll 4
        for (int j = 0; j < 64; j++) {
            const int kidx = kb * 64 + j;
            float s;
            if (kidx > qi) {
                s = -1e30f;
            } else {
                float d0 = 0.f;
#pragma unroll
                for (int d = 0; d < 64; d += 4) {
                    float4 kv = *(const float4*)&KV[j][d];
                    d0 += qreg[d] * kv.x + qreg[d + 1] * kv.y
                        + qreg[d + 2] * kv.z + qreg[d + 3] * kv.w;
                }
                s = d0 * 0.125f;   // 1/sqrt(64)
            }
            Sc[t][j] = s;
            mtile = fmaxf(mtile, s);
        }

        const float mnew = fmaxf(m, mtile);
        const float corr = __expf(m - mnew);   // 0 when m == -inf
        l *= corr;
#pragma unroll
        for (int d = 0; d < 64; d++) acc[d] *= corr;
        m = mnew;

        __syncthreads();   // everyone done reading K tile
        // --- load V tile into same buffer ---
#pragma unroll
        for (int i = 0; i < 16; i++) {
            int idx = t + i * 64;
            int j = idx >> 4, d4 = (idx & 15) << 2;
            *(float4*)&KV[j][d4] = *(const float4*)(v + tbase + (size_t)j * DM + d4);
        }
        __syncthreads();

        // --- pass 2: probs + V accumulation ---
#pragma unroll 2
        for (int j = 0; j < 64; j++) {
            const float sv = Sc[t][j];
            const float p = (sv > -1e29f) ? __expf(sv - m) : 0.f;
            l += p;
#pragma unroll
            for (int d = 0; d < 64; d += 4) {
                float4 vv = *(const float4*)&KV[j][d];
                acc[d]     += p * vv.x;
                acc[d + 1] += p * vv.y;
                acc[d + 2] += p * vv.z;
                acc[d + 3] += p * vv.w;
            }
        }
    }

    const float inv = 1.f / l;
#pragma unroll
    for (int d = 0; d < 64; d += 4) {
        float4 x;
        x.x = acc[d] * inv;     x.y = acc[d + 1] * inv;
        x.z = acc[d + 2] * inv; x.w = acc[d + 3] * inv;
        *(float4*)(o + qrow + d) = x;
    }
}

// ---------------------------------------------------------------------------
extern "C" void kernel_launch(void* const* d_in, const int* in_sizes, int n_in,
                              void* d_out, int out_size) {
    const float* x  = (const float*)d_in[0];
    const float* Wq = (const float*)d_in[1];
    const float* Wk = (const float*)d_in[2];
    const float* Wv = (const float*)d_in[3];
    const float* Wo = (const float*)d_in[4];
    float* out = (float*)d_out;

    float *q, *k, *v, *a;
    cudaGetSymbolAddress((void**)&q, g_q);
    cudaGetSymbolAddress((void**)&k, g_k);
    cudaGetSymbolAddress((void**)&v, g_v);
    cudaGetSymbolAddress((void**)&a, g_attn);

    dim3 gg(S_TOTAL / 128, DM / 128);   // (64, 8)
    gemm_nt<<<gg, 256>>>(x, Wq, q, S_TOTAL, DM, DM);
    gemm_nt<<<gg, 256>>>(x, Wk, k, S_TOTAL, DM, DM);
    gemm_nt<<<gg, 256>>>(x, Wv, v, S_TOTAL, DM, DM);

    attn_kernel<<<dim3(CHUNKL / 64, NHEAD, NCHUNK), 64>>>(q, k, v, a);

    gemm_nt<<<gg, 256>>>(a, Wo, out, S_TOTAL, DM, DM);
}

// round 5
// speedup vs baseline: 1.5068x; 1.5068x over previous
#include <cuda_runtime.h>
#include <cuda_bf16.h>
#include <math.h>
#include <stdint.h>

#define S_TOTAL 8192
#define DM      1024
#define NHEAD   16
#define HDIM    64
#define CHUNKL  2048
#define NCHUNK  4

// ---------------- scratch (allocation-free rule: __device__ globals) --------
__device__ float g_q[S_TOTAL * DM];
__device__ float g_k[S_TOTAL * DM];
__device__ float g_v[S_TOTAL * DM];
__device__ float g_attn[S_TOTAL * DM];
__device__ __nv_bfloat16 g_xhi[S_TOTAL * DM];
__device__ __nv_bfloat16 g_xlo[S_TOTAL * DM];
__device__ __nv_bfloat16 g_ahi[S_TOTAL * DM];
__device__ __nv_bfloat16 g_alo[S_TOTAL * DM];
__device__ __nv_bfloat16 g_whi[4 * DM * DM];
__device__ __nv_bfloat16 g_wlo[4 * DM * DM];

// ---------------- warp-mma helpers (plain sm_103-safe PTX) ------------------
__device__ __forceinline__ uint32_t smem_u32(const void* p) {
    uint32_t a;
    asm("{ .reg .u64 t; cvta.to.shared.u64 t, %1; cvt.u32.u64 %0, t; }" : "=r"(a) : "l"(p));
    return a;
}
__device__ __forceinline__ void ldsm_x4(uint32_t* r, uint32_t addr) {
    asm volatile("ldmatrix.sync.aligned.m8n8.x4.shared.b16 {%0,%1,%2,%3}, [%4];"
                 : "=r"(r[0]), "=r"(r[1]), "=r"(r[2]), "=r"(r[3]) : "r"(addr));
}
__device__ __forceinline__ void mma_bf16(float* c, const uint32_t* a, const uint32_t* b) {
    asm volatile("mma.sync.aligned.m16n8k16.row.col.f32.bf16.bf16.f32 "
                 "{%0,%1,%2,%3}, {%4,%5,%6,%7}, {%8,%9}, {%0,%1,%2,%3};"
                 : "+f"(c[0]), "+f"(c[1]), "+f"(c[2]), "+f"(c[3])
                 : "r"(a[0]), "r"(a[1]), "r"(a[2]), "r"(a[3]), "r"(b[0]), "r"(b[1]));
}

// ---------------- fp32 -> bf16 hi/lo split ----------------------------------
__global__ void __launch_bounds__(256) split_hi_lo(const float* __restrict__ src,
                                                   __nv_bfloat16* __restrict__ hi,
                                                   __nv_bfloat16* __restrict__ lo,
                                                   int n4) {
    int i = blockIdx.x * 256 + threadIdx.x;
    if (i >= n4) return;
    float4 v = ((const float4*)src)[i];
    float f[4] = {v.x, v.y, v.z, v.w};
    __align__(8) __nv_bfloat16 h[4], l[4];
#pragma unroll
    for (int j = 0; j < 4; j++) {
        h[j] = __float2bfloat16(f[j]);
        l[j] = __float2bfloat16(f[j] - __bfloat162float(h[j]));
    }
    ((uint2*)hi)[i] = *(uint2*)h;
    ((uint2*)lo)[i] = *(uint2*)l;
}

// ---------------- mma.sync GEMM: C[m,n] = sum_k A[m,k]*B[n,k] ---------------
// hi/lo bf16 decomposition: C = AhiBhi + AhiBlo + AloBhi (fp32 accum).
// Block 128(M)x64(N), BK=32. 8 warps as 2(M)x4(N); warp tile 64x16.
// Smem rows padded to 40 bf16 (80B): rows 0..7 hit distinct banks for ldmatrix.
#define BM 128
#define BN 64
#define BKC 32
#define PAD_ROW 40   /* bf16 elems per smem row (80 bytes) */

__global__ void __launch_bounds__(256) gemm_mma(
    const __nv_bfloat16* __restrict__ Ahi, const __nv_bfloat16* __restrict__ Alo,
    const __nv_bfloat16* __restrict__ Bhi, const __nv_bfloat16* __restrict__ Blo,
    float* __restrict__ C, int M, int N, int K) {

    __shared__ __align__(16) __nv_bfloat16 sA[2][BM * PAD_ROW];  // [hi,lo]
    __shared__ __align__(16) __nv_bfloat16 sB[2][BN * PAD_ROW];

    const int tid  = threadIdx.x;
    const int lane = tid & 31;
    const int warp = tid >> 5;
    const int wm = (warp & 1) * 64;     // warp M offset
    const int wn = (warp >> 1) * 16;    // warp N offset
    const int bm = blockIdx.x, bn = blockIdx.y;

    const uint32_t aBase[2] = {smem_u32(&sA[0][0]), smem_u32(&sA[1][0])};
    const uint32_t bBase[2] = {smem_u32(&sB[0][0]), smem_u32(&sB[1][0])};

    // ldmatrix lane offsets (bytes)
    const uint32_t arow_off = (uint32_t)(wm + (lane & 15)) * 80 + (lane >> 4) * 16;
    const uint32_t bn_off =
        (uint32_t)(wn + (lane & 7) + ((lane >> 4) << 3)) * 80 + ((lane >> 3) & 1) * 16;

    float c[4][2][4];
#pragma unroll
    for (int i = 0; i < 4; i++)
#pragma unroll
        for (int j = 0; j < 2; j++)
#pragma unroll
            for (int t = 0; t < 4; t++) c[i][j][t] = 0.f;

    const __nv_bfloat16* aSrc[2] = {Ahi, Alo};
    const __nv_bfloat16* bSrc[2] = {Bhi, Blo};

    for (int kc = 0; kc < K; kc += BKC) {
        __syncthreads();   // previous tile fully consumed
        // ---- A tiles: 128 rows x 32 bf16 (4 x 16B per row) ----
#pragma unroll
        for (int s = 0; s < 2; s++) {
#pragma unroll
            for (int it = 0; it < 2; it++) {
                int id = tid + it * 256;          // 0..511
                int row = id >> 2, c16 = (id & 3) * 16;
                uint4 v = *(const uint4*)(aSrc[s] + (size_t)(bm * BM + row) * K + kc + (c16 >> 1));
                *(uint4*)((char*)&sA[s][0] + row * 80 + c16) = v;
            }
            // ---- B tile: 64 rows ----
            {
                int row = tid >> 2, c16 = (tid & 3) * 16;
                uint4 v = *(const uint4*)(bSrc[s] + (size_t)(bn * BN + row) * K + kc + (c16 >> 1));
                *(uint4*)((char*)&sB[s][0] + row * 80 + c16) = v;
            }
        }
        __syncthreads();

#pragma unroll
        for (int ks = 0; ks < 2; ks++) {           // two k16 steps per chunk
            uint32_t ah[4][4], al[4][4], bh[4], bl[4];
#pragma unroll
            for (int mt = 0; mt < 4; mt++)
                ldsm_x4(ah[mt], aBase[0] + arow_off + mt * (16 * 80) + ks * 32);
            ldsm_x4(bh, bBase[0] + bn_off + ks * 32);
#pragma unroll
            for (int mt = 0; mt < 4; mt++)
                ldsm_x4(al[mt], aBase[1] + arow_off + mt * (16 * 80) + ks * 32);
            ldsm_x4(bl, bBase[1] + bn_off + ks * 32);

#pragma unroll
            for (int mt = 0; mt < 4; mt++)
#pragma unroll
                for (int nt = 0; nt < 2; nt++) {
                    mma_bf16(c[mt][nt], ah[mt], &bh[nt * 2]);   // hi*hi
                    mma_bf16(c[mt][nt], ah[mt], &bl[nt * 2]);   // hi*lo
                    mma_bf16(c[mt][nt], al[mt], &bh[nt * 2]);   // lo*hi
                }
        }
    }

    // ---- epilogue ----
    const int r0 = bm * BM + wm + (lane >> 2);
    const int c0 = bn * BN + wn + (lane & 3) * 2;
#pragma unroll
    for (int mt = 0; mt < 4; mt++)
#pragma unroll
        for (int nt = 0; nt < 2; nt++) {
            const int row = r0 + mt * 16;
            const int col = c0 + nt * 8;
            *(float2*)&C[(size_t)row * N + col]       = make_float2(c[mt][nt][0], c[mt][nt][1]);
            *(float2*)&C[(size_t)(row + 8) * N + col] = make_float2(c[mt][nt][2], c[mt][nt][3]);
        }
}

// ---------------- chunk-local causal attention (fp32) -----------------------
__global__ void __launch_bounds__(64) attn_kernel(const float* __restrict__ q,
                                                  const float* __restrict__ k,
                                                  const float* __restrict__ v,
                                                  float* __restrict__ o) {
    __shared__ float KV[64][64];
    __shared__ float Sc[64][65];

    const int t  = threadIdx.x;
    const int qb = blockIdx.x;
    const int h  = blockIdx.y;
    const int ch = blockIdx.z;

    const int    qi   = qb * 64 + t;
    const size_t qrow = (size_t)(ch * CHUNKL + qi) * DM + h * HDIM;

    float qreg[64];
#pragma unroll
    for (int d = 0; d < 64; d += 4) {
        float4 x = *(const float4*)(q + qrow + d);
        qreg[d] = x.x; qreg[d + 1] = x.y; qreg[d + 2] = x.z; qreg[d + 3] = x.w;
    }

    float m = -INFINITY, l = 0.f;
    float acc[64];
#pragma unroll
    for (int d = 0; d < 64; d++) acc[d] = 0.f;

    for (int kb = 0; kb <= qb; kb++) {
        const size_t tbase = (size_t)(ch * CHUNKL + kb * 64) * DM + h * HDIM;

        __syncthreads();
#pragma unroll
        for (int i = 0; i < 16; i++) {
            int idx = t + i * 64;
            int j = idx >> 4, d4 = (idx & 15) << 2;
            *(float4*)&KV[j][d4] = *(const float4*)(k + tbase + (size_t)j * DM + d4);
        }
        __syncthreads();

        float mtile = -INFINITY;
#pragma unroll 4
        for (int j = 0; j < 64; j++) {
            const int kidx = kb * 64 + j;
            float s;
            if (kidx > qi) {
                s = -1e30f;
            } else {
                float d0 = 0.f;
#pragma unroll
                for (int d = 0; d < 64; d += 4) {
                    float4 kv = *(const float4*)&KV[j][d];
                    d0 += qreg[d] * kv.x + qreg[d + 1] * kv.y
                        + qreg[d + 2] * kv.z + qreg[d + 3] * kv.w;
                }
                s = d0 * 0.125f;
            }
            Sc[t][j] = s;
            mtile = fmaxf(mtile, s);
        }

        const float mnew = fmaxf(m, mtile);
        const float corr = __expf(m - mnew);
        l *= corr;
#pragma unroll
        for (int d = 0; d < 64; d++) acc[d] *= corr;
        m = mnew;

        __syncthreads();
#pragma unroll
        for (int i = 0; i < 16; i++) {
            int idx = t + i * 64;
            int j = idx >> 4, d4 = (idx & 15) << 2;
            *(float4*)&KV[j][d4] = *(const float4*)(v + tbase + (size_t)j * DM + d4);
        }
        __syncthreads();

#pragma unroll 2
        for (int j = 0; j < 64; j++) {
            const float sv = Sc[t][j];
            const float p = (sv > -1e29f) ? __expf(sv - m) : 0.f;
            l += p;
#pragma unroll
            for (int d = 0; d < 64; d += 4) {
                float4 vv = *(const float4*)&KV[j][d];
                acc[d]     += p * vv.x;
                acc[d + 1] += p * vv.y;
                acc[d + 2] += p * vv.z;
                acc[d + 3] += p * vv.w;
            }
        }
    }

    const float inv = 1.f / l;
#pragma unroll
    for (int d = 0; d < 64; d += 4) {
        float4 x;
        x.x = acc[d] * inv;     x.y = acc[d + 1] * inv;
        x.z = acc[d + 2] * inv; x.w = acc[d + 3] * inv;
        *(float4*)(o + qrow + d) = x;
    }
}

// ---------------------------------------------------------------------------
extern "C" void kernel_launch(void* const* d_in, const int* in_sizes, int n_in,
                              void* d_out, int out_size) {
    const float* x  = (const float*)d_in[0];
    const float* Wq = (const float*)d_in[1];
    const float* Wk = (const float*)d_in[2];
    const float* Wv = (const float*)d_in[3];
    const float* Wo = (const float*)d_in[4];
    float* out = (float*)d_out;

    float *q, *k, *v, *a;
    __nv_bfloat16 *xhi, *xlo, *ahi, *alo, *whi, *wlo;
    cudaGetSymbolAddress((void**)&q, g_q);
    cudaGetSymbolAddress((void**)&k, g_k);
    cudaGetSymbolAddress((void**)&v, g_v);
    cudaGetSymbolAddress((void**)&a, g_attn);
    cudaGetSymbolAddress((void**)&xhi, g_xhi);
    cudaGetSymbolAddress((void**)&xlo, g_xlo);
    cudaGetSymbolAddress((void**)&ahi, g_ahi);
    cudaGetSymbolAddress((void**)&alo, g_alo);
    cudaGetSymbolAddress((void**)&whi, g_whi);
    cudaGetSymbolAddress((void**)&wlo, g_wlo);

    const int nx4 = S_TOTAL * DM / 4;
    const int nw4 = DM * DM / 4;
    const float* Ws[4] = {Wq, Wk, Wv, Wo};

    split_hi_lo<<<(nx4 + 255) / 256, 256>>>(x, xhi, xlo, nx4);
    for (int i = 0; i < 4; i++)
        split_hi_lo<<<(nw4 + 255) / 256, 256>>>(Ws[i], whi + (size_t)i * DM * DM,
                                                wlo + (size_t)i * DM * DM, nw4);

    dim3 gg(S_TOTAL / BM, DM / BN);   // (64, 16)
    gemm_mma<<<gg, 256>>>(xhi, xlo, whi + 0 * (size_t)DM * DM,
                          wlo + 0 * (size_t)DM * DM, q, S_TOTAL, DM, DM);
    gemm_mma<<<gg, 256>>>(xhi, xlo, whi + 1 * (size_t)DM * DM,
                          wlo + 1 * (size_t)DM * DM, k, S_TOTAL, DM, DM);
    gemm_mma<<<gg, 256>>>(xhi, xlo, whi + 2 * (size_t)DM * DM,
                          wlo + 2 * (size_t)DM * DM, v, S_TOTAL, DM, DM);

    attn_kernel<<<dim3(CHUNKL / 64, NHEAD, NCHUNK), 64>>>(q, k, v, a);

    split_hi_lo<<<(nx4 + 255) / 256, 256>>>(a, ahi, alo, nx4);
    gemm_mma<<<gg, 256>>>(ahi, alo, whi + 3 * (size_t)DM * DM,
                          wlo + 3 * (size_t)DM * DM, out, S_TOTAL, DM, DM);
}